// round 1
// baseline (speedup 1.0000x reference)
#include <cuda_runtime.h>

// Problem dims (fixed by the reference)
#define BB 8
#define CC 256
#define NN 2048

// Scratch (no allocations allowed -> __device__ globals)
__device__ float g_q[BB * CC * NN];     // 16 MB
__device__ float g_k[BB * CC * NN];     // 16 MB
__device__ float g_v[BB * CC * NN];     // 16 MB
__device__ float g_M[BB * CC * CC];     // 2 MB   M[b] = V_b @ Q_b^T
__device__ float g_partial[BB * CC];    // per-(b,c) qsum*ksum
__device__ float g_inv;                 // 1/S

// ---------------------------------------------------------------------------
// Kernel 1: q/k/v = W @ x_b + bias   (NN GEMM, M=256, K=256, N=2048)
// 64x64 tile, BK=16, 256 threads, 4x4 microtile.
// blockIdx.z = b*3 + which  (which: 0=q,1=k,2=v)
// ---------------------------------------------------------------------------
__global__ __launch_bounds__(256) void att_qkv_kernel(
    const float* __restrict__ x,
    const float* __restrict__ Wq, const float* __restrict__ bq,
    const float* __restrict__ Wk, const float* __restrict__ bk,
    const float* __restrict__ Wv, const float* __restrict__ bv)
{
    const int bz = blockIdx.z;
    const int b  = bz / 3;
    const int w  = bz - 3 * b;

    const float* W    = (w == 0) ? Wq : ((w == 1) ? Wk : Wv);
    const float* bias = (w == 0) ? bq : ((w == 1) ? bk : bv);
    float* out        = (w == 0) ? g_q : ((w == 1) ? g_k : g_v);

    const float* X = x + (size_t)b * CC * NN;
    out += (size_t)b * CC * NN;

    __shared__ float sA[16][64];   // [k][m]
    __shared__ float sB[16][64];   // [k][n]

    const int tid  = threadIdx.x;
    const int trow = tid >> 4;       // 0..15
    const int tcol = tid & 15;       // 0..15
    const int m0 = blockIdx.y * 64;
    const int n0 = blockIdx.x * 64;

    // A-load: thread loads float4 of W row (m0+am), k-offset ak
    const int am = tid >> 2;            // 0..63
    const int ak = (tid & 3) << 2;      // 0,4,8,12
    // B-load: row kb (0..15), col bn
    const int kb = tid >> 4;            // 0..15
    const int bn = (tid & 15) << 2;     // 0..60

    float acc[4][4] = {};

    for (int k0 = 0; k0 < CC; k0 += 16) {
        float4 av = *reinterpret_cast<const float4*>(&W[(size_t)(m0 + am) * CC + k0 + ak]);
        sA[ak + 0][am] = av.x; sA[ak + 1][am] = av.y;
        sA[ak + 2][am] = av.z; sA[ak + 3][am] = av.w;
        float4 bv4 = *reinterpret_cast<const float4*>(&X[(size_t)(k0 + kb) * NN + n0 + bn]);
        *reinterpret_cast<float4*>(&sB[kb][bn]) = bv4;
        __syncthreads();
#pragma unroll
        for (int kk = 0; kk < 16; kk++) {
            float4 a  = *reinterpret_cast<const float4*>(&sA[kk][trow << 2]);
            float4 bb = *reinterpret_cast<const float4*>(&sB[kk][tcol << 2]);
            float ar[4] = {a.x, a.y, a.z, a.w};
            float br[4] = {bb.x, bb.y, bb.z, bb.w};
#pragma unroll
            for (int i = 0; i < 4; i++)
#pragma unroll
                for (int j = 0; j < 4; j++)
                    acc[i][j] += ar[i] * br[j];
        }
        __syncthreads();
    }

#pragma unroll
    for (int i = 0; i < 4; i++) {
        const int m = m0 + (trow << 2) + i;
        const float bi = bias[m];
        float4 r;
        r.x = acc[i][0] + bi; r.y = acc[i][1] + bi;
        r.z = acc[i][2] + bi; r.w = acc[i][3] + bi;
        *reinterpret_cast<float4*>(&out[(size_t)m * NN + n0 + (tcol << 2)]) = r;
    }
}

// ---------------------------------------------------------------------------
// Kernel 2: per-(b,c) row sums of q and k, product -> g_partial
// ---------------------------------------------------------------------------
__global__ __launch_bounds__(256) void att_rowsum_kernel()
{
    const int idx = blockIdx.x;            // 0 .. B*C-1
    const float* qr = g_q + (size_t)idx * NN;
    const float* kr = g_k + (size_t)idx * NN;
    float sq = 0.f, sk = 0.f;
    for (int n = threadIdx.x; n < NN; n += 256) { sq += qr[n]; sk += kr[n]; }
    __shared__ float rq[256], rk[256];
    rq[threadIdx.x] = sq; rk[threadIdx.x] = sk;
    __syncthreads();
    for (int s = 128; s > 0; s >>= 1) {
        if (threadIdx.x < s) {
            rq[threadIdx.x] += rq[threadIdx.x + s];
            rk[threadIdx.x] += rk[threadIdx.x + s];
        }
        __syncthreads();
    }
    if (threadIdx.x == 0) g_partial[idx] = rq[0] * rk[0];
}

// ---------------------------------------------------------------------------
// Kernel 3: S = sum(partials) (double accum, deterministic tree), g_inv = 1/S
// ---------------------------------------------------------------------------
__global__ __launch_bounds__(256) void att_reduce_s_kernel()
{
    __shared__ double sd[256];
    double s = 0.0;
    for (int i = threadIdx.x; i < BB * CC; i += 256) s += (double)g_partial[i];
    sd[threadIdx.x] = s;
    __syncthreads();
    for (int st = 128; st > 0; st >>= 1) {
        if (threadIdx.x < st) sd[threadIdx.x] += sd[threadIdx.x + st];
        __syncthreads();
    }
    if (threadIdx.x == 0) g_inv = (float)(1.0 / sd[0]);
}

// ---------------------------------------------------------------------------
// Kernel 4: M[b] = V_b @ Q_b^T   (NT GEMM, M=N=256, K=2048)
// ---------------------------------------------------------------------------
__global__ __launch_bounds__(256) void att_vq_kernel()
{
    const int b = blockIdx.z;
    const float* V = g_v + (size_t)b * CC * NN;
    const float* Q = g_q + (size_t)b * CC * NN;
    float* M = g_M + (size_t)b * CC * CC;

    __shared__ float sA[16][64];   // [k][c1]
    __shared__ float sB[16][64];   // [k][c2]

    const int tid  = threadIdx.x;
    const int trow = tid >> 4;
    const int tcol = tid & 15;
    const int m0 = blockIdx.y * 64;
    const int n0 = blockIdx.x * 64;

    const int am = tid >> 2;
    const int ak = (tid & 3) << 2;

    float acc[4][4] = {};

    for (int k0 = 0; k0 < NN; k0 += 16) {
        float4 av = *reinterpret_cast<const float4*>(&V[(size_t)(m0 + am) * NN + k0 + ak]);
        sA[ak + 0][am] = av.x; sA[ak + 1][am] = av.y;
        sA[ak + 2][am] = av.z; sA[ak + 3][am] = av.w;
        float4 bv4 = *reinterpret_cast<const float4*>(&Q[(size_t)(n0 + am) * NN + k0 + ak]);
        sB[ak + 0][am] = bv4.x; sB[ak + 1][am] = bv4.y;
        sB[ak + 2][am] = bv4.z; sB[ak + 3][am] = bv4.w;
        __syncthreads();
#pragma unroll
        for (int kk = 0; kk < 16; kk++) {
            float4 a  = *reinterpret_cast<const float4*>(&sA[kk][trow << 2]);
            float4 bb = *reinterpret_cast<const float4*>(&sB[kk][tcol << 2]);
            float ar[4] = {a.x, a.y, a.z, a.w};
            float br[4] = {bb.x, bb.y, bb.z, bb.w};
#pragma unroll
            for (int i = 0; i < 4; i++)
#pragma unroll
                for (int j = 0; j < 4; j++)
                    acc[i][j] += ar[i] * br[j];
        }
        __syncthreads();
    }

#pragma unroll
    for (int i = 0; i < 4; i++) {
        const int m = m0 + (trow << 2) + i;
        float4 r;
        r.x = acc[i][0]; r.y = acc[i][1]; r.z = acc[i][2]; r.w = acc[i][3];
        *reinterpret_cast<float4*>(&M[(size_t)m * CC + n0 + (tcol << 2)]) = r;
    }
}

// ---------------------------------------------------------------------------
// Kernel 5: out[b] = (M[b] @ K_b) * (1/S)   (NN GEMM, M=256, K=256, N=2048)
// ---------------------------------------------------------------------------
__global__ __launch_bounds__(256) void att_out_kernel(float* __restrict__ outp)
{
    const int b = blockIdx.z;
    const float* A  = g_M + (size_t)b * CC * CC;
    const float* Bk = g_k + (size_t)b * CC * NN;
    float* O = outp + (size_t)b * CC * NN;
    const float inv = g_inv;

    __shared__ float sA[16][64];
    __shared__ float sB[16][64];

    const int tid  = threadIdx.x;
    const int trow = tid >> 4;
    const int tcol = tid & 15;
    const int m0 = blockIdx.y * 64;
    const int n0 = blockIdx.x * 64;

    const int am = tid >> 2;
    const int ak = (tid & 3) << 2;
    const int kb = tid >> 4;
    const int bn = (tid & 15) << 2;

    float acc[4][4] = {};

    for (int k0 = 0; k0 < CC; k0 += 16) {
        float4 av = *reinterpret_cast<const float4*>(&A[(size_t)(m0 + am) * CC + k0 + ak]);
        sA[ak + 0][am] = av.x; sA[ak + 1][am] = av.y;
        sA[ak + 2][am] = av.z; sA[ak + 3][am] = av.w;
        float4 bv4 = *reinterpret_cast<const float4*>(&Bk[(size_t)(k0 + kb) * NN + n0 + bn]);
        *reinterpret_cast<float4*>(&sB[kb][bn]) = bv4;
        __syncthreads();
#pragma unroll
        for (int kk = 0; kk < 16; kk++) {
            float4 a  = *reinterpret_cast<const float4*>(&sA[kk][trow << 2]);
            float4 bb = *reinterpret_cast<const float4*>(&sB[kk][tcol << 2]);
            float ar[4] = {a.x, a.y, a.z, a.w};
            float br[4] = {bb.x, bb.y, bb.z, bb.w};
#pragma unroll
            for (int i = 0; i < 4; i++)
#pragma unroll
                for (int j = 0; j < 4; j++)
                    acc[i][j] += ar[i] * br[j];
        }
        __syncthreads();
    }

#pragma unroll
    for (int i = 0; i < 4; i++) {
        const int m = m0 + (trow << 2) + i;
        float4 r;
        r.x = acc[i][0] * inv; r.y = acc[i][1] * inv;
        r.z = acc[i][2] * inv; r.w = acc[i][3] * inv;
        *reinterpret_cast<float4*>(&O[(size_t)m * NN + n0 + (tcol << 2)]) = r;
    }
}

// ---------------------------------------------------------------------------
// Launch
// ---------------------------------------------------------------------------
extern "C" void kernel_launch(void* const* d_in, const int* in_sizes, int n_in,
                              void* d_out, int out_size)
{
    const float* x  = (const float*)d_in[0];
    const float* Wq = (const float*)d_in[1];
    const float* bq = (const float*)d_in[2];
    const float* Wk = (const float*)d_in[3];
    const float* bk = (const float*)d_in[4];
    const float* Wv = (const float*)d_in[5];
    const float* bv = (const float*)d_in[6];
    float* out = (float*)d_out;

    // 1) q,k,v projections: grid (N/64, C/64, B*3)
    dim3 g1(NN / 64, CC / 64, BB * 3);
    att_qkv_kernel<<<g1, 256>>>(x, Wq, bq, Wk, bk, Wv, bv);

    // 2) row sums -> partials
    att_rowsum_kernel<<<BB * CC, 256>>>();

    // 3) S reduction -> 1/S
    att_reduce_s_kernel<<<1, 256>>>();

    // 4) M[b] = V Q^T : grid (C/64, C/64, B)
    dim3 g2(CC / 64, CC / 64, BB);
    att_vq_kernel<<<g2, 256>>>();

    // 5) out = M K / S : grid (N/64, C/64, B)
    dim3 g3(NN / 64, CC / 64, BB);
    att_out_kernel<<<g3, 256>>>(out);
}